// round 12
// baseline (speedup 1.0000x reference)
#include <cuda_runtime.h>
#include <cuda_bf16.h>
#include <cstdint>

typedef unsigned int u32;

#define SQ   2048
#define DH   64
#define NBLK 32
#define L2E  1.4426950408889634f
#define BIG  (1e6f * L2E)

// static smem 48KB = 3 stage buffers of 16KB. Buffer 0 doubles as the Q
// staging area during the prologue (Q fragments hoisted to registers first).
#define OFF_QHI 0
#define OFF_QLO 8192
#define ST_KHI  0
#define ST_KLO  4096
#define ST_VHI  8192
#define ST_VLO  12288

// pre-converted, pre-swizzled bf16 hi/lo tiles: [bh][kb] -> 8KB tile,
// 128B rows, keys [h*32,h*32+32) contiguous 4KB.
#define TILE_B 8192
__device__ __align__(16) char KHI_g[16 * 32 * TILE_B];
__device__ __align__(16) char KLO_g[16 * 32 * TILE_B];
__device__ __align__(16) char VHI_g[16 * 32 * TILE_B];
__device__ __align__(16) char VLO_g[16 * 32 * TILE_B];

__device__ __forceinline__ u32 swz(u32 x) { return x ^ ((x >> 3) & 0x70u); }
__device__ __forceinline__ u32 smem_u32(const void* p) {
    u32 a;
    asm("{ .reg .u64 t; cvta.to.shared.u64 t, %1; cvt.u32.u64 %0, t; }" : "=r"(a) : "l"(p));
    return a;
}
__device__ __forceinline__ float ex2(float x) {
    float r; asm("ex2.approx.f32 %0, %1;" : "=f"(r) : "f"(x)); return r;
}
__device__ __forceinline__ u32 bf2pack(float e0, float e1) {   // e0 -> low half
    u32 r; asm("cvt.rn.bf16x2.f32 %0, %1, %2;" : "=r"(r) : "f"(e1), "f"(e0)); return r;
}
__device__ __forceinline__ float bfrnd(float x) {
    return __bfloat162float(__float2bfloat16(x));
}
__device__ __forceinline__ void split4(float4 v, u32& h0, u32& h1, u32& l0, u32& l1) {
    h0 = bf2pack(v.x, v.y);
    h1 = bf2pack(v.z, v.w);
    l0 = bf2pack(v.x - bfrnd(v.x), v.y - bfrnd(v.y));
    l1 = bf2pack(v.z - bfrnd(v.z), v.w - bfrnd(v.w));
}
__device__ __forceinline__ void ldsm4(u32 a, u32& r0, u32& r1, u32& r2, u32& r3) {
    asm volatile("ldmatrix.sync.aligned.m8n8.x4.shared.b16 {%0,%1,%2,%3},[%4];"
                 : "=r"(r0), "=r"(r1), "=r"(r2), "=r"(r3) : "r"(a));
}
__device__ __forceinline__ void ldsm4t(u32 a, u32& r0, u32& r1, u32& r2, u32& r3) {
    asm volatile("ldmatrix.sync.aligned.m8n8.x4.trans.shared.b16 {%0,%1,%2,%3},[%4];"
                 : "=r"(r0), "=r"(r1), "=r"(r2), "=r"(r3) : "r"(a));
}
// not volatile — lets ptxas interleave independent-accumulator HMMAs
__device__ __forceinline__ void mma_bf(float* c, const u32* a, u32 b0, u32 b1) {
    asm("mma.sync.aligned.m16n8k16.row.col.f32.bf16.bf16.f32 "
        "{%0,%1,%2,%3},{%4,%5,%6,%7},{%8,%9},{%0,%1,%2,%3};"
        : "+f"(c[0]), "+f"(c[1]), "+f"(c[2]), "+f"(c[3])
        : "r"(a[0]), "r"(a[1]), "r"(a[2]), "r"(a[3]), "r"(b0), "r"(b1));
}
__device__ __forceinline__ void cpasync16(u32 dst, const void* src) {
    asm volatile("cp.async.cg.shared.global [%0], [%1], 16;" :: "r"(dst), "l"(src));
}

// ---- pre-pass: K/V fp32 -> bf16 hi/lo, swizzled 8KB tiles in global ----
__global__ void __launch_bounds__(128)
prepass(const float* __restrict__ K, const float* __restrict__ V)
{
    const int kb = blockIdx.x, bh = blockIdx.y;
    const int tid = threadIdx.x;
    const int row = tid >> 1, cb = (tid & 1) * 32;
    const size_t src = ((size_t)bh * SQ + (size_t)kb * 64 + row) * DH + cb;
    const float4* ks = (const float4*)(K + src);
    const float4* vs = (const float4*)(V + src);
    const size_t tb = (size_t)(bh * NBLK + kb) * TILE_B;
    const u32 rb = (u32)row * 128u + (u32)cb * 2u;
    #pragma unroll
    for (int i = 0; i < 8; ++i) {
        u32 h0, h1, l0, l1;
        u32 a = swz(rb + i * 8);
        split4(ks[i], h0, h1, l0, l1);
        *(uint2*)(KHI_g + tb + a) = make_uint2(h0, h1);
        *(uint2*)(KLO_g + tb + a) = make_uint2(l0, l1);
        split4(vs[i], h0, h1, l0, l1);
        *(uint2*)(VHI_g + tb + a) = make_uint2(h0, h1);
        *(uint2*)(VLO_g + tb + a) = make_uint2(l0, l1);
    }
}

// Block-sparse flash attention: bf16 3-term split HMMA, hoisted Q fragments,
// 3-stage cp.async pipeline, cross-stage interleave: S(n+1) runs inside PV(n)
// (independent accumulators/buffers -> 2x MMA-level ILP per stage).
__global__ void __launch_bounds__(128, 4)
bma_hmma(const float* __restrict__ Q, const float* __restrict__ Mk,
         const int* __restrict__ Mat, float* __restrict__ Out)
{
    __shared__ __align__(16) char smc[49152];
    const u32 smb = smem_u32(smc);

    const int tid  = threadIdx.x;
    const int lane = tid & 31;
    const int wid  = tid >> 5;
    const int gid  = lane >> 2;
    const int tig  = lane & 3;
    const int mbase = wid * 16;
    const int qb   = blockIdx.x;
    const int bh   = blockIdx.y;
    const int b    = bh >> 3;

    const float* Qp   = Q + ((size_t)bh * SQ + (size_t)qb * 64) * DH;
    const float* mrow = Mk + (size_t)b * SQ;
    const int* matrow = Mat + qb * NBLK;

    // ---- Q split into smem (buffer-0 region), then hoist fragments ----
    {
        int row = tid >> 1, cb = (tid & 1) * 32;
        const float4* qs = (const float4*)(Qp + row * DH + cb);
        u32 rb = (u32)row * 128u + (u32)cb * 2u;
        #pragma unroll
        for (int i = 0; i < 8; ++i) {
            u32 h0, h1, l0, l1; split4(qs[i], h0, h1, l0, l1);
            u32 a = swz(rb + i * 8);
            *(uint2*)(smc + OFF_QHI + a) = make_uint2(h0, h1);
            *(uint2*)(smc + OFF_QLO + a) = make_uint2(l0, l1);
        }
    }
    __syncthreads();

    const u32 aoffRow = (u32)(mbase + (lane & 15)) * 128u;
    const u32 aoffCol = (u32)((lane >> 4) * 8) * 2u;
    u32 qah[4][4], qal[4][4];                 // loop-invariant Q fragments
    #pragma unroll
    for (int ks = 0; ks < 4; ++ks) {
        u32 aoff = swz(aoffRow + (u32)(ks * 32) + aoffCol);
        ldsm4(smb + OFF_QHI + aoff, qah[ks][0], qah[ks][1], qah[ks][2], qah[ks][3]);
        ldsm4(smb + OFF_QLO + aoff, qal[ks][0], qal[ks][1], qal[ks][2], qal[ks][3]);
    }
    __syncthreads();   // Q reads done; buffer 0 free for stage fetches

    float oacc[8][4];
    #pragma unroll
    for (int t = 0; t < 8; ++t)
        #pragma unroll
        for (int j = 0; j < 4; ++j) oacc[t][j] = 0.f;
    float lac0 = 0.f, lac1 = 0.f;
    float sacc[4][4];

    const u32 cpoff = (u32)tid * 32u;          // 4KB / 128 threads

    auto issue_stage = [&](int kb, int half, int sbuf) {
        const size_t g = (size_t)(bh * NBLK + kb) * TILE_B + (size_t)half * 4096 + cpoff;
        const u32 d = smb + (u32)sbuf * 16384u + cpoff;
        cpasync16(d + ST_KHI,      KHI_g + g);
        cpasync16(d + ST_KHI + 16, KHI_g + g + 16);
        cpasync16(d + ST_KLO,      KLO_g + g);
        cpasync16(d + ST_KLO + 16, KLO_g + g + 16);
        cpasync16(d + ST_VHI,      VHI_g + g);
        cpasync16(d + ST_VHI + 16, VHI_g + g + 16);
        cpasync16(d + ST_VLO,      VLO_g + g);
        cpasync16(d + ST_VLO + 16, VLO_g + g + 16);
    };
    auto advance = [&](int& kb, int& hf) {
        hf ^= 1;
        if (hf == 0) { ++kb; while (kb < NBLK && matrow[kb] == 0) ++kb; }
    };
    // one 16-row k-slab of S(n+1): 6 ldsm + 12 MMAs
    auto s_block = [&](u32 stb, int ks) {
        u32 kh[2][4], kl[2][4];
        #pragma unroll
        for (int g = 0; g < 2; ++g) {
            u32 boff = swz(
                (u32)(g * 16 + ((lane >> 4) & 1) * 8 + (lane & 7)) * 128u +
                (u32)(ks * 16 + ((lane >> 3) & 1) * 8) * 2u);
            ldsm4(stb + ST_KHI + boff, kh[g][0], kh[g][1], kh[g][2], kh[g][3]);
            ldsm4(stb + ST_KLO + boff, kl[g][0], kl[g][1], kl[g][2], kl[g][3]);
        }
        mma_bf(sacc[0], qah[ks], kh[0][0], kh[0][1]);
        mma_bf(sacc[1], qah[ks], kh[0][2], kh[0][3]);
        mma_bf(sacc[2], qah[ks], kh[1][0], kh[1][1]);
        mma_bf(sacc[3], qah[ks], kh[1][2], kh[1][3]);
        mma_bf(sacc[0], qah[ks], kl[0][0], kl[0][1]);
        mma_bf(sacc[1], qah[ks], kl[0][2], kl[0][3]);
        mma_bf(sacc[2], qah[ks], kl[1][0], kl[1][1]);
        mma_bf(sacc[3], qah[ks], kl[1][2], kl[1][3]);
        mma_bf(sacc[0], qal[ks], kh[0][0], kh[0][1]);
        mma_bf(sacc[1], qal[ks], kh[0][2], kh[0][3]);
        mma_bf(sacc[2], qal[ks], kh[1][0], kh[1][1]);
        mma_bf(sacc[3], qal[ks], kh[1][2], kh[1][3]);
    };
    // one (16-key, 16-d) PV block: 2 ldsm + 6 MMAs
    auto pv_block = [&](u32 stb, const u32 (&pah)[2][4], const u32 (&pal)[2][4],
                        int s, int dt) {
        u32 voff = swz(
            (u32)(s * 16 + ((lane >> 3) & 1) * 8 + (lane & 7)) * 128u +
            (u32)(dt * 16 + ((lane >> 4) & 1) * 8) * 2u);
        u32 vh0, vh1, vh2, vh3, vl0, vl1, vl2, vl3;
        ldsm4t(stb + ST_VHI + voff, vh0, vh1, vh2, vh3);
        ldsm4t(stb + ST_VLO + voff, vl0, vl1, vl2, vl3);
        mma_bf(oacc[dt*2],   pah[s], vh0, vh1);
        mma_bf(oacc[dt*2+1], pah[s], vh2, vh3);
        mma_bf(oacc[dt*2],   pah[s], vl0, vl1);
        mma_bf(oacc[dt*2+1], pah[s], vl2, vl3);
        mma_bf(oacc[dt*2],   pal[s], vh0, vh1);
        mma_bf(oacc[dt*2+1], pal[s], vh2, vh3);
    };

    // ---- prologue: fetch stages 0,1; compute S(0) ----
    int ckb = 0; while (matrow[ckb] == 0) ++ckb;
    int chf = 0;
    int fkb = ckb, fhf = 0;
    issue_stage(fkb, fhf, 0);
    asm volatile("cp.async.commit_group;" ::: "memory");
    advance(fkb, fhf);                           // stage 1 always exists (hf pair)
    issue_stage(fkb, fhf, 1);
    asm volatile("cp.async.commit_group;" ::: "memory");
    advance(fkb, fhf);
    asm volatile("cp.async.wait_group 1;" ::: "memory");
    __syncthreads();

    #pragma unroll
    for (int t = 0; t < 4; ++t)
        #pragma unroll
        for (int j = 0; j < 4; ++j) sacc[t][j] = 0.f;
    #pragma unroll
    for (int ks = 0; ks < 4; ++ks) s_block(smb, ks);   // buf 0

    int cbuf = 0;

    // ---- main loop: softmax(n); fetch(n+2); PV(n) interleaved with S(n+1) ----
    #pragma unroll 1
    while (true) {
        // softmax on sacc -> P fragments (bf16 hi/lo)
        u32 pah[2][4], pal[2][4];
        #pragma unroll
        for (int nt = 0; nt < 4; ++nt) {
            const float2 mb =
                *(const float2*)(mrow + ckb * 64 + chf * 32 + nt * 8 + 2 * tig);
            float b0 = (mb.x - 1.f) * BIG;
            float b1 = (mb.y - 1.f) * BIG;
            float p0 = ex2(fmaf(sacc[nt][0], L2E, b0));
            float p1 = ex2(fmaf(sacc[nt][1], L2E, b1));
            float p2 = ex2(fmaf(sacc[nt][2], L2E, b0));
            float p3 = ex2(fmaf(sacc[nt][3], L2E, b1));
            lac0 += p0 + p1;
            lac1 += p2 + p3;
            int s = nt >> 1, hb = (nt & 1) * 2;
            pah[s][hb+0] = bf2pack(p0, p1);
            pah[s][hb+1] = bf2pack(p2, p3);
            pal[s][hb+0] = bf2pack(p0 - bfrnd(p0), p1 - bfrnd(p1));
            pal[s][hb+1] = bf2pack(p2 - bfrnd(p2), p3 - bfrnd(p3));
        }

        int nkb = ckb, nhf = chf; advance(nkb, nhf);
        const bool has_next = (nkb < NBLK);

        asm volatile("cp.async.wait_group 0;" ::: "memory");  // f(n+1) done
        __syncthreads();  // visibility of all slices; prev-iter buf reads done
        if (fkb < NBLK) {
            issue_stage(fkb, fhf, (cbuf + 2) % 3);
            asm volatile("cp.async.commit_group;" ::: "memory");
            advance(fkb, fhf);
        }

        const u32 cstb = smb + (u32)cbuf * 16384u;
        if (has_next) {
            const u32 nstb = smb + (u32)((cbuf + 1) % 3) * 16384u;
            #pragma unroll
            for (int t = 0; t < 4; ++t)
                #pragma unroll
                for (int j = 0; j < 4; ++j) sacc[t][j] = 0.f;
            // interleave: S(n+1) slabs between PV(n) blocks
            #pragma unroll
            for (int u = 0; u < 4; ++u) {
                s_block(nstb, u);
                pv_block(cstb, pah, pal, u >> 1, (u & 1) * 2);
                pv_block(cstb, pah, pal, u >> 1, (u & 1) * 2 + 1);
            }
            ckb = nkb; chf = nhf;
            cbuf = (cbuf == 2) ? 0 : cbuf + 1;
        } else {
            #pragma unroll
            for (int u = 0; u < 4; ++u) {
                pv_block(cstb, pah, pal, u >> 1, (u & 1) * 2);
                pv_block(cstb, pah, pal, u >> 1, (u & 1) * 2 + 1);
            }
            break;
        }
    }

    // ---- epilogue: quad-reduce l, O/l, store ----
    lac0 += __shfl_xor_sync(0xffffffffu, lac0, 1);
    lac0 += __shfl_xor_sync(0xffffffffu, lac0, 2);
    lac1 += __shfl_xor_sync(0xffffffffu, lac1, 1);
    lac1 += __shfl_xor_sync(0xffffffffu, lac1, 2);
    const float inv0 = 1.f / lac0;
    const float inv1 = 1.f / lac1;

    const int q0 = qb * 64 + mbase + gid;
    float* o0 = Out + ((size_t)bh * SQ + q0) * DH;
    float* o1 = o0 + 8 * DH;
    #pragma unroll
    for (int dt = 0; dt < 8; ++dt) {
        int col = dt * 8 + 2 * tig;
        *(float2*)(o0 + col) = make_float2(oacc[dt][0] * inv0, oacc[dt][1] * inv0);
        *(float2*)(o1 + col) = make_float2(oacc[dt][2] * inv1, oacc[dt][3] * inv1);
    }
}

extern "C" void kernel_launch(void* const* d_in, const int* in_sizes, int n_in,
                              void* d_out, int out_size)
{
    const float* q    = (const float*)d_in[0];
    const float* k    = (const float*)d_in[1];
    const float* v    = (const float*)d_in[2];
    const float* mask = (const float*)d_in[3];
    const int*   mat  = (const int*)  d_in[4];
    float* out = (float*)d_out;

    dim3 pgrid(NBLK, 16);
    prepass<<<pgrid, 128>>>(k, v);
    dim3 grid(NBLK, 16);   // 32 q-blocks x 16 bh; 4 CTAs/SM, one wave
    bma_hmma<<<grid, 128>>>(q, mask, mat, out);
}

// round 13
// speedup vs baseline: 1.1005x; 1.1005x over previous
#include <cuda_runtime.h>
#include <cuda_bf16.h>
#include <cstdint>

typedef unsigned int u32;

#define SQ   2048
#define DH   64
#define NBLK 32
#define L2E  1.4426950408889634f
#define BIG  (1e6f * L2E)

// static smem 48KB: Q hi/lo (16KB) + 2 K/V stage buffers (16KB each)
#define OFF_QHI 0
#define OFF_QLO 8192
#define OFF_ST  16384
#define ST_KHI  0
#define ST_KLO  4096
#define ST_VHI  8192
#define ST_VLO  12288

// pre-converted, pre-swizzled bf16 hi/lo tiles: [bh][kb] -> 8KB tile,
// 128B rows, keys [h*32,h*32+32) contiguous 4KB.
#define TILE_B 8192
__device__ __align__(16) char KHI_g[16 * 32 * TILE_B];
__device__ __align__(16) char KLO_g[16 * 32 * TILE_B];
__device__ __align__(16) char VHI_g[16 * 32 * TILE_B];
__device__ __align__(16) char VLO_g[16 * 32 * TILE_B];

// split-K partials: unnormalized O and l per (split, bh, q)
__device__ __align__(16) float OPART[2][16 * SQ * DH];
__device__ float LPART[2][16 * SQ];

__device__ __forceinline__ u32 swz(u32 x) { return x ^ ((x >> 3) & 0x70u); }
__device__ __forceinline__ u32 smem_u32(const void* p) {
    u32 a;
    asm("{ .reg .u64 t; cvta.to.shared.u64 t, %1; cvt.u32.u64 %0, t; }" : "=r"(a) : "l"(p));
    return a;
}
__device__ __forceinline__ float ex2(float x) {
    float r; asm("ex2.approx.f32 %0, %1;" : "=f"(r) : "f"(x)); return r;
}
__device__ __forceinline__ u32 bf2pack(float e0, float e1) {   // e0 -> low half
    u32 r; asm("cvt.rn.bf16x2.f32 %0, %1, %2;" : "=r"(r) : "f"(e1), "f"(e0)); return r;
}
__device__ __forceinline__ float bfrnd(float x) {
    return __bfloat162float(__float2bfloat16(x));
}
__device__ __forceinline__ void split4(float4 v, u32& h0, u32& h1, u32& l0, u32& l1) {
    h0 = bf2pack(v.x, v.y);
    h1 = bf2pack(v.z, v.w);
    l0 = bf2pack(v.x - bfrnd(v.x), v.y - bfrnd(v.y));
    l1 = bf2pack(v.z - bfrnd(v.z), v.w - bfrnd(v.w));
}
__device__ __forceinline__ void ldsm4(u32 a, u32& r0, u32& r1, u32& r2, u32& r3) {
    asm volatile("ldmatrix.sync.aligned.m8n8.x4.shared.b16 {%0,%1,%2,%3},[%4];"
                 : "=r"(r0), "=r"(r1), "=r"(r2), "=r"(r3) : "r"(a));
}
__device__ __forceinline__ void ldsm4t(u32 a, u32& r0, u32& r1, u32& r2, u32& r3) {
    asm volatile("ldmatrix.sync.aligned.m8n8.x4.trans.shared.b16 {%0,%1,%2,%3},[%4];"
                 : "=r"(r0), "=r"(r1), "=r"(r2), "=r"(r3) : "r"(a));
}
// not volatile — lets ptxas interleave independent-accumulator HMMAs
__device__ __forceinline__ void mma_bf(float* c, const u32* a, u32 b0, u32 b1) {
    asm("mma.sync.aligned.m16n8k16.row.col.f32.bf16.bf16.f32 "
        "{%0,%1,%2,%3},{%4,%5,%6,%7},{%8,%9},{%0,%1,%2,%3};"
        : "+f"(c[0]), "+f"(c[1]), "+f"(c[2]), "+f"(c[3])
        : "r"(a[0]), "r"(a[1]), "r"(a[2]), "r"(a[3]), "r"(b0), "r"(b1));
}
__device__ __forceinline__ void cpasync16(u32 dst, const void* src) {
    asm volatile("cp.async.cg.shared.global [%0], [%1], 16;" :: "r"(dst), "l"(src));
}

// ---- pre-pass: K/V fp32 -> bf16 hi/lo, swizzled 8KB tiles in global ----
__global__ void __launch_bounds__(128)
prepass(const float* __restrict__ K, const float* __restrict__ V)
{
    const int kb = blockIdx.x, bh = blockIdx.y;
    const int tid = threadIdx.x;
    const int row = tid >> 1, cb = (tid & 1) * 32;
    const size_t src = ((size_t)bh * SQ + (size_t)kb * 64 + row) * DH + cb;
    const float4* ks = (const float4*)(K + src);
    const float4* vs = (const float4*)(V + src);
    const size_t tb = (size_t)(bh * NBLK + kb) * TILE_B;
    const u32 rb = (u32)row * 128u + (u32)cb * 2u;
    #pragma unroll
    for (int i = 0; i < 8; ++i) {
        u32 h0, h1, l0, l1;
        u32 a = swz(rb + i * 8);
        split4(ks[i], h0, h1, l0, l1);
        *(uint2*)(KHI_g + tb + a) = make_uint2(h0, h1);
        *(uint2*)(KLO_g + tb + a) = make_uint2(l0, l1);
        split4(vs[i], h0, h1, l0, l1);
        *(uint2*)(VHI_g + tb + a) = make_uint2(h0, h1);
        *(uint2*)(VLO_g + tb + a) = make_uint2(l0, l1);
    }
}

// Block-sparse flash attention (R9 structure), split-K by key-block parity.
// CTA (qb, bh, sp) processes key blocks kb with kb%2==sp; writes unnormalized
// partials to OPART/LPART. 2-buffer cp.async pipeline, bf16 3-term HMMA.
__global__ void __launch_bounds__(128, 4)
bma_hmma(const float* __restrict__ Q, const float* __restrict__ Mk,
         const int* __restrict__ Mat)
{
    __shared__ __align__(16) char smc[49152];
    const u32 smb = smem_u32(smc);

    const int tid  = threadIdx.x;
    const int lane = tid & 31;
    const int wid  = tid >> 5;
    const int gid  = lane >> 2;
    const int tig  = lane & 3;
    const int mbase = wid * 16;
    const int qb   = blockIdx.x;
    const int bh   = blockIdx.y;
    const int sp   = blockIdx.z;     // key-block parity split
    const int b    = bh >> 3;

    const float* Qp   = Q + ((size_t)bh * SQ + (size_t)qb * 64) * DH;
    const float* mrow = Mk + (size_t)b * SQ;
    const int* matrow = Mat + qb * NBLK;

    // ---- Q split -> Qhi/Qlo bf16, swizzled (once per CTA) ----
    {
        int row = tid >> 1, cb = (tid & 1) * 32;
        const float4* qs = (const float4*)(Qp + row * DH + cb);
        u32 rb = (u32)row * 128u + (u32)cb * 2u;
        #pragma unroll
        for (int i = 0; i < 8; ++i) {
            u32 h0, h1, l0, l1; split4(qs[i], h0, h1, l0, l1);
            u32 a = swz(rb + i * 8);
            *(uint2*)(smc + OFF_QHI + a) = make_uint2(h0, h1);
            *(uint2*)(smc + OFF_QLO + a) = make_uint2(l0, l1);
        }
    }

    float oacc[8][4];
    #pragma unroll
    for (int t = 0; t < 8; ++t)
        #pragma unroll
        for (int j = 0; j < 4; ++j) oacc[t][j] = 0.f;
    float lac0 = 0.f, lac1 = 0.f;

    const u32 aoffRow = (u32)(mbase + (lane & 15)) * 128u;
    const u32 aoffCol = (u32)((lane >> 4) * 8) * 2u;
    const u32 cpoff = (u32)tid * 32u;          // 4KB / 128 threads

    auto issue_stage = [&](int kb, int half, int sbuf) {
        const size_t g = (size_t)(bh * NBLK + kb) * TILE_B + (size_t)half * 4096 + cpoff;
        const u32 d = smb + OFF_ST + (u32)sbuf * 16384u + cpoff;
        cpasync16(d + ST_KHI,      KHI_g + g);
        cpasync16(d + ST_KHI + 16, KHI_g + g + 16);
        cpasync16(d + ST_KLO,      KLO_g + g);
        cpasync16(d + ST_KLO + 16, KLO_g + g + 16);
        cpasync16(d + ST_VHI,      VHI_g + g);
        cpasync16(d + ST_VHI + 16, VHI_g + g + 16);
        cpasync16(d + ST_VLO,      VLO_g + g);
        cpasync16(d + ST_VLO + 16, VLO_g + g + 16);
    };
    auto advance = [&](int& kb, int& hf) {
        hf ^= 1;
        if (hf == 0) { kb += 2; while (kb < NBLK && matrow[kb] == 0) kb += 2; }
    };

    // first active block of this parity (may not exist)
    int cur_kb = sp;
    while (cur_kb < NBLK && matrow[cur_kb] == 0) cur_kb += 2;
    int cur_half = 0;
    int buf = 0;

    if (cur_kb < NBLK) issue_stage(cur_kb, 0, 0);
    asm volatile("cp.async.commit_group;" ::: "memory");

    #pragma unroll 1
    while (cur_kb < NBLK) {
        int n_kb = cur_kb, n_half = cur_half;
        advance(n_kb, n_half);

        __syncthreads();                       // buf^1 free (prev stage consumed)
        if (n_kb < NBLK) issue_stage(n_kb, n_half, buf ^ 1);
        asm volatile("cp.async.commit_group;" ::: "memory");
        asm volatile("cp.async.wait_group 1;" ::: "memory");   // current arrived
        __syncthreads();

        const u32 stb = smb + OFF_ST + (u32)buf * 16384u;

        // ---- S = Q @ K^T (bf16, 3-term) ----
        float sacc[4][4];
        #pragma unroll
        for (int t = 0; t < 4; ++t)
            #pragma unroll
            for (int j = 0; j < 4; ++j) sacc[t][j] = 0.f;

        #pragma unroll
        for (int ks = 0; ks < 4; ++ks) {
            u32 ah[4], al[4];
            u32 aoff = swz(aoffRow + (u32)(ks * 16) * 2u + aoffCol);
            ldsm4(smb + OFF_QHI + aoff, ah[0], ah[1], ah[2], ah[3]);
            ldsm4(smb + OFF_QLO + aoff, al[0], al[1], al[2], al[3]);
            u32 kh[2][4], kl[2][4];
            #pragma unroll
            for (int g = 0; g < 2; ++g) {
                u32 boff = swz(
                    (u32)(g * 16 + ((lane >> 4) & 1) * 8 + (lane & 7)) * 128u +
                    (u32)(ks * 16 + ((lane >> 3) & 1) * 8) * 2u);
                ldsm4(stb + ST_KHI + boff, kh[g][0], kh[g][1], kh[g][2], kh[g][3]);
                ldsm4(stb + ST_KLO + boff, kl[g][0], kl[g][1], kl[g][2], kl[g][3]);
            }
            mma_bf(sacc[0], ah, kh[0][0], kh[0][1]);
            mma_bf(sacc[1], ah, kh[0][2], kh[0][3]);
            mma_bf(sacc[2], ah, kh[1][0], kh[1][1]);
            mma_bf(sacc[3], ah, kh[1][2], kh[1][3]);
            mma_bf(sacc[0], ah, kl[0][0], kl[0][1]);
            mma_bf(sacc[1], ah, kl[0][2], kl[0][3]);
            mma_bf(sacc[2], ah, kl[1][0], kl[1][1]);
            mma_bf(sacc[3], ah, kl[1][2], kl[1][3]);
            mma_bf(sacc[0], al, kh[0][0], kh[0][1]);
            mma_bf(sacc[1], al, kh[0][2], kh[0][3]);
            mma_bf(sacc[2], al, kh[1][0], kh[1][1]);
            mma_bf(sacc[3], al, kh[1][2], kh[1][3]);
        }

        // ---- softmax; P packed to bf16 hi/lo A-fragments in-register ----
        u32 pah[2][4], pal[2][4];
        #pragma unroll
        for (int nt = 0; nt < 4; ++nt) {
            const float2 mb =
                *(const float2*)(mrow + cur_kb * 64 + cur_half * 32 + nt * 8 + 2 * tig);
            float b0 = (mb.x - 1.f) * BIG;
            float b1 = (mb.y - 1.f) * BIG;
            float p0 = ex2(fmaf(sacc[nt][0], L2E, b0));
            float p1 = ex2(fmaf(sacc[nt][1], L2E, b1));
            float p2 = ex2(fmaf(sacc[nt][2], L2E, b0));
            float p3 = ex2(fmaf(sacc[nt][3], L2E, b1));
            lac0 += p0 + p1;
            lac1 += p2 + p3;
            int s = nt >> 1, hb = (nt & 1) * 2;
            pah[s][hb+0] = bf2pack(p0, p1);
            pah[s][hb+1] = bf2pack(p2, p3);
            pal[s][hb+0] = bf2pack(p0 - bfrnd(p0), p1 - bfrnd(p1));
            pal[s][hb+1] = bf2pack(p2 - bfrnd(p2), p3 - bfrnd(p3));
        }

        // ---- O += P @ V (bf16, 3-term) ----
        #pragma unroll
        for (int s = 0; s < 2; ++s) {
            #pragma unroll
            for (int dt = 0; dt < 4; ++dt) {
                u32 voff = swz(
                    (u32)(s * 16 + ((lane >> 3) & 1) * 8 + (lane & 7)) * 128u +
                    (u32)(dt * 16 + ((lane >> 4) & 1) * 8) * 2u);
                u32 vh0, vh1, vh2, vh3, vl0, vl1, vl2, vl3;
                ldsm4t(stb + ST_VHI + voff, vh0, vh1, vh2, vh3);
                ldsm4t(stb + ST_VLO + voff, vl0, vl1, vl2, vl3);
                mma_bf(oacc[dt*2],   pah[s], vh0, vh1);
                mma_bf(oacc[dt*2+1], pah[s], vh2, vh3);
                mma_bf(oacc[dt*2],   pah[s], vl0, vl1);
                mma_bf(oacc[dt*2+1], pah[s], vl2, vl3);
                mma_bf(oacc[dt*2],   pal[s], vh0, vh1);
                mma_bf(oacc[dt*2+1], pal[s], vh2, vh3);
            }
        }

        cur_kb = n_kb; cur_half = n_half; buf ^= 1;
    }

    // ---- epilogue: quad-reduce l, write UNNORMALIZED partials ----
    lac0 += __shfl_xor_sync(0xffffffffu, lac0, 1);
    lac0 += __shfl_xor_sync(0xffffffffu, lac0, 2);
    lac1 += __shfl_xor_sync(0xffffffffu, lac1, 1);
    lac1 += __shfl_xor_sync(0xffffffffu, lac1, 2);

    const int q0 = qb * 64 + mbase + gid;
    float* o0 = OPART[sp] + ((size_t)bh * SQ + q0) * DH;
    float* o1 = o0 + 8 * DH;
    #pragma unroll
    for (int dt = 0; dt < 8; ++dt) {
        int col = dt * 8 + 2 * tig;
        *(float2*)(o0 + col) = make_float2(oacc[dt][0], oacc[dt][1]);
        *(float2*)(o1 + col) = make_float2(oacc[dt][2], oacc[dt][3]);
    }
    if (tig == 0) {
        LPART[sp][bh * SQ + q0]     = lac0;
        LPART[sp][bh * SQ + q0 + 8] = lac1;
    }
}

// ---- combine: Out = (O0+O1) / (l0+l1) ----
__global__ void __launch_bounds__(256)
combine(float* __restrict__ Out)
{
    int t = blockIdx.x * 256 + threadIdx.x;   // float4 index (16 per q-row)
    int qrow = t >> 4;
    float inv = 1.f / (LPART[0][qrow] + LPART[1][qrow]);
    float4 a = ((const float4*)OPART[0])[t];
    float4 b = ((const float4*)OPART[1])[t];
    float4 r = make_float4((a.x + b.x) * inv, (a.y + b.y) * inv,
                           (a.z + b.z) * inv, (a.w + b.w) * inv);
    ((float4*)Out)[t] = r;
}

extern "C" void kernel_launch(void* const* d_in, const int* in_sizes, int n_in,
                              void* d_out, int out_size)
{
    const float* q    = (const float*)d_in[0];
    const float* k    = (const float*)d_in[1];
    const float* v    = (const float*)d_in[2];
    const float* mask = (const float*)d_in[3];
    const int*   mat  = (const int*)  d_in[4];
    float* out = (float*)d_out;

    dim3 pgrid(NBLK, 16);
    prepass<<<pgrid, 128>>>(k, v);
    dim3 grid(NBLK, 16, 2);   // split-K parity: 1024 half-size CTAs
    bma_hmma<<<grid, 128>>>(q, mask, mat);
    combine<<<(16 * SQ * DH / 4) / 256, 256>>>(out);
}

// round 14
// speedup vs baseline: 1.1903x; 1.0816x over previous
#include <cuda_runtime.h>
#include <cuda_bf16.h>
#include <cstdint>

typedef unsigned int u32;

#define SQ   2048
#define DH   64
#define NBLK 32
#define L2E  1.4426950408889634f
#define BIG  (1e6f * L2E)

// static smem 48KB: Q hi/lo (16KB) + 2 K/V stage buffers (16KB each)
#define OFF_QHI 0
#define OFF_QLO 8192
#define OFF_ST  16384
#define ST_KHI  0
#define ST_KLO  4096
#define ST_VHI  8192
#define ST_VLO  12288

// pre-converted, pre-swizzled bf16 hi/lo tiles: [bh][kb] -> 8KB tile,
// 128B rows, keys [h*32,h*32+32) contiguous 4KB.
#define TILE_B 8192
__device__ __align__(16) char KHI_g[16 * 32 * TILE_B];
__device__ __align__(16) char KLO_g[16 * 32 * TILE_B];
__device__ __align__(16) char VHI_g[16 * 32 * TILE_B];
__device__ __align__(16) char VLO_g[16 * 32 * TILE_B];

// split-K partials: unnormalized O and l per (split, bh, q)
__device__ __align__(16) float OPART[2][16 * SQ * DH];
__device__ float LPART[2][16 * SQ];

__device__ __forceinline__ u32 swz(u32 x) { return x ^ ((x >> 3) & 0x70u); }
__device__ __forceinline__ u32 smem_u32(const void* p) {
    u32 a;
    asm("{ .reg .u64 t; cvta.to.shared.u64 t, %1; cvt.u32.u64 %0, t; }" : "=r"(a) : "l"(p));
    return a;
}
__device__ __forceinline__ float ex2(float x) {
    float r; asm("ex2.approx.f32 %0, %1;" : "=f"(r) : "f"(x)); return r;
}
__device__ __forceinline__ u32 bf2pack(float e0, float e1) {   // e0 -> low half
    u32 r; asm("cvt.rn.bf16x2.f32 %0, %1, %2;" : "=r"(r) : "f"(e1), "f"(e0)); return r;
}
__device__ __forceinline__ float bfrnd(float x) {
    return __bfloat162float(__float2bfloat16(x));
}
__device__ __forceinline__ void split4(float4 v, u32& h0, u32& h1, u32& l0, u32& l1) {
    h0 = bf2pack(v.x, v.y);
    h1 = bf2pack(v.z, v.w);
    l0 = bf2pack(v.x - bfrnd(v.x), v.y - bfrnd(v.y));
    l1 = bf2pack(v.z - bfrnd(v.z), v.w - bfrnd(v.w));
}
__device__ __forceinline__ void ldsm4(u32 a, u32& r0, u32& r1, u32& r2, u32& r3) {
    asm volatile("ldmatrix.sync.aligned.m8n8.x4.shared.b16 {%0,%1,%2,%3},[%4];"
                 : "=r"(r0), "=r"(r1), "=r"(r2), "=r"(r3) : "r"(a));
}
__device__ __forceinline__ void ldsm4t(u32 a, u32& r0, u32& r1, u32& r2, u32& r3) {
    asm volatile("ldmatrix.sync.aligned.m8n8.x4.trans.shared.b16 {%0,%1,%2,%3},[%4];"
                 : "=r"(r0), "=r"(r1), "=r"(r2), "=r"(r3) : "r"(a));
}
// not volatile — lets ptxas interleave independent-accumulator HMMAs
__device__ __forceinline__ void mma_bf(float* c, const u32* a, u32 b0, u32 b1) {
    asm("mma.sync.aligned.m16n8k16.row.col.f32.bf16.bf16.f32 "
        "{%0,%1,%2,%3},{%4,%5,%6,%7},{%8,%9},{%0,%1,%2,%3};"
        : "+f"(c[0]), "+f"(c[1]), "+f"(c[2]), "+f"(c[3])
        : "r"(a[0]), "r"(a[1]), "r"(a[2]), "r"(a[3]), "r"(b0), "r"(b1));
}
__device__ __forceinline__ void cpasync16(u32 dst, const void* src) {
    asm volatile("cp.async.cg.shared.global [%0], [%1], 16;" :: "r"(dst), "l"(src));
}

// ---- pre-pass v2: high-parallelism K/V fp32 -> bf16 hi/lo swizzled tiles.
// grid (NBLK, 16, 4): each CTA converts 16 rows; each thread 2+2 float4.
__global__ void __launch_bounds__(128)
prepass(const float* __restrict__ K, const float* __restrict__ V)
{
    const int kb = blockIdx.x, bh = blockIdx.y, zz = blockIdx.z;
    const int tid = threadIdx.x;
    const int row = zz * 16 + (tid >> 3);      // key row within 64
    const int c8  = tid & 7;                   // 8 threads per row
    const size_t src = ((size_t)bh * SQ + (size_t)kb * 64 + row) * DH + c8 * 8;
    const float4* ks = (const float4*)(K + src);
    const float4* vs = (const float4*)(V + src);
    const size_t tb = (size_t)(bh * NBLK + kb) * TILE_B;
    const u32 rb = (u32)row * 128u + (u32)c8 * 16u;
    #pragma unroll
    for (int i = 0; i < 2; ++i) {
        u32 h0, h1, l0, l1;
        u32 a = swz(rb + i * 8);
        split4(ks[i], h0, h1, l0, l1);
        *(uint2*)(KHI_g + tb + a) = make_uint2(h0, h1);
        *(uint2*)(KLO_g + tb + a) = make_uint2(l0, l1);
        split4(vs[i], h0, h1, l0, l1);
        *(uint2*)(VHI_g + tb + a) = make_uint2(h0, h1);
        *(uint2*)(VLO_g + tb + a) = make_uint2(l0, l1);
    }
}

// Block-sparse flash attention (R9 structure), split-K by key-block parity.
// CTA (qb, bh, sp) processes key blocks kb with kb%2==sp; writes unnormalized
// partials to OPART/LPART. 2-buffer cp.async pipeline, bf16 3-term HMMA.
__global__ void __launch_bounds__(128, 4)
bma_hmma(const float* __restrict__ Q, const float* __restrict__ Mk,
         const int* __restrict__ Mat)
{
    __shared__ __align__(16) char smc[49152];
    const u32 smb = smem_u32(smc);

    const int tid  = threadIdx.x;
    const int lane = tid & 31;
    const int wid  = tid >> 5;
    const int gid  = lane >> 2;
    const int tig  = lane & 3;
    const int mbase = wid * 16;
    const int qb   = blockIdx.x;
    const int bh   = blockIdx.y;
    const int sp   = blockIdx.z;     // key-block parity split
    const int b    = bh >> 3;

    const float* Qp   = Q + ((size_t)bh * SQ + (size_t)qb * 64) * DH;
    const float* mrow = Mk + (size_t)b * SQ;
    const int* matrow = Mat + qb * NBLK;

    // ---- Q split -> Qhi/Qlo bf16, swizzled (once per CTA) ----
    {
        int row = tid >> 1, cb = (tid & 1) * 32;
        const float4* qs = (const float4*)(Qp + row * DH + cb);
        u32 rb = (u32)row * 128u + (u32)cb * 2u;
        #pragma unroll
        for (int i = 0; i < 8; ++i) {
            u32 h0, h1, l0, l1; split4(qs[i], h0, h1, l0, l1);
            u32 a = swz(rb + i * 8);
            *(uint2*)(smc + OFF_QHI + a) = make_uint2(h0, h1);
            *(uint2*)(smc + OFF_QLO + a) = make_uint2(l0, l1);
        }
    }

    float oacc[8][4];
    #pragma unroll
    for (int t = 0; t < 8; ++t)
        #pragma unroll
        for (int j = 0; j < 4; ++j) oacc[t][j] = 0.f;
    float lac0 = 0.f, lac1 = 0.f;

    const u32 aoffRow = (u32)(mbase + (lane & 15)) * 128u;
    const u32 aoffCol = (u32)((lane >> 4) * 8) * 2u;
    const u32 cpoff = (u32)tid * 32u;          // 4KB / 128 threads

    auto issue_stage = [&](int kb, int half, int sbuf) {
        const size_t g = (size_t)(bh * NBLK + kb) * TILE_B + (size_t)half * 4096 + cpoff;
        const u32 d = smb + OFF_ST + (u32)sbuf * 16384u + cpoff;
        cpasync16(d + ST_KHI,      KHI_g + g);
        cpasync16(d + ST_KHI + 16, KHI_g + g + 16);
        cpasync16(d + ST_KLO,      KLO_g + g);
        cpasync16(d + ST_KLO + 16, KLO_g + g + 16);
        cpasync16(d + ST_VHI,      VHI_g + g);
        cpasync16(d + ST_VHI + 16, VHI_g + g + 16);
        cpasync16(d + ST_VLO,      VLO_g + g);
        cpasync16(d + ST_VLO + 16, VLO_g + g + 16);
    };
    auto advance = [&](int& kb, int& hf) {
        hf ^= 1;
        if (hf == 0) { kb += 2; while (kb < NBLK && matrow[kb] == 0) kb += 2; }
    };

    // first active block of this parity (may not exist)
    int cur_kb = sp;
    while (cur_kb < NBLK && matrow[cur_kb] == 0) cur_kb += 2;
    int cur_half = 0;
    int buf = 0;

    if (cur_kb < NBLK) issue_stage(cur_kb, 0, 0);
    asm volatile("cp.async.commit_group;" ::: "memory");

    #pragma unroll 1
    while (cur_kb < NBLK) {
        int n_kb = cur_kb, n_half = cur_half;
        advance(n_kb, n_half);

        __syncthreads();                       // buf^1 free (prev stage consumed)
        if (n_kb < NBLK) issue_stage(n_kb, n_half, buf ^ 1);
        asm volatile("cp.async.commit_group;" ::: "memory");
        asm volatile("cp.async.wait_group 1;" ::: "memory");   // current arrived
        __syncthreads();

        const u32 stb = smb + OFF_ST + (u32)buf * 16384u;

        // ---- S = Q @ K^T (bf16, 3-term) ----
        float sacc[4][4];
        #pragma unroll
        for (int t = 0; t < 4; ++t)
            #pragma unroll
            for (int j = 0; j < 4; ++j) sacc[t][j] = 0.f;

        #pragma unroll
        for (int ks = 0; ks < 4; ++ks) {
            u32 ah[4], al[4];
            u32 aoff = swz(aoffRow + (u32)(ks * 16) * 2u + aoffCol);
            ldsm4(smb + OFF_QHI + aoff, ah[0], ah[1], ah[2], ah[3]);
            ldsm4(smb + OFF_QLO + aoff, al[0], al[1], al[2], al[3]);
            u32 kh[2][4], kl[2][4];
            #pragma unroll
            for (int g = 0; g < 2; ++g) {
                u32 boff = swz(
                    (u32)(g * 16 + ((lane >> 4) & 1) * 8 + (lane & 7)) * 128u +
                    (u32)(ks * 16 + ((lane >> 3) & 1) * 8) * 2u);
                ldsm4(stb + ST_KHI + boff, kh[g][0], kh[g][1], kh[g][2], kh[g][3]);
                ldsm4(stb + ST_KLO + boff, kl[g][0], kl[g][1], kl[g][2], kl[g][3]);
            }
            mma_bf(sacc[0], ah, kh[0][0], kh[0][1]);
            mma_bf(sacc[1], ah, kh[0][2], kh[0][3]);
            mma_bf(sacc[2], ah, kh[1][0], kh[1][1]);
            mma_bf(sacc[3], ah, kh[1][2], kh[1][3]);
            mma_bf(sacc[0], ah, kl[0][0], kl[0][1]);
            mma_bf(sacc[1], ah, kl[0][2], kl[0][3]);
            mma_bf(sacc[2], ah, kl[1][0], kl[1][1]);
            mma_bf(sacc[3], ah, kl[1][2], kl[1][3]);
            mma_bf(sacc[0], al, kh[0][0], kh[0][1]);
            mma_bf(sacc[1], al, kh[0][2], kh[0][3]);
            mma_bf(sacc[2], al, kh[1][0], kh[1][1]);
            mma_bf(sacc[3], al, kh[1][2], kh[1][3]);
        }

        // ---- softmax; P packed to bf16 hi/lo A-fragments in-register ----
        u32 pah[2][4], pal[2][4];
        #pragma unroll
        for (int nt = 0; nt < 4; ++nt) {
            const float2 mb =
                *(const float2*)(mrow + cur_kb * 64 + cur_half * 32 + nt * 8 + 2 * tig);
            float b0 = (mb.x - 1.f) * BIG;
            float b1 = (mb.y - 1.f) * BIG;
            float p0 = ex2(fmaf(sacc[nt][0], L2E, b0));
            float p1 = ex2(fmaf(sacc[nt][1], L2E, b1));
            float p2 = ex2(fmaf(sacc[nt][2], L2E, b0));
            float p3 = ex2(fmaf(sacc[nt][3], L2E, b1));
            lac0 += p0 + p1;
            lac1 += p2 + p3;
            int s = nt >> 1, hb = (nt & 1) * 2;
            pah[s][hb+0] = bf2pack(p0, p1);
            pah[s][hb+1] = bf2pack(p2, p3);
            pal[s][hb+0] = bf2pack(p0 - bfrnd(p0), p1 - bfrnd(p1));
            pal[s][hb+1] = bf2pack(p2 - bfrnd(p2), p3 - bfrnd(p3));
        }

        // ---- O += P @ V (bf16, 3-term) ----
        #pragma unroll
        for (int s = 0; s < 2; ++s) {
            #pragma unroll
            for (int dt = 0; dt < 4; ++dt) {
                u32 voff = swz(
                    (u32)(s * 16 + ((lane >> 3) & 1) * 8 + (lane & 7)) * 128u +
                    (u32)(dt * 16 + ((lane >> 4) & 1) * 8) * 2u);
                u32 vh0, vh1, vh2, vh3, vl0, vl1, vl2, vl3;
                ldsm4t(stb + ST_VHI + voff, vh0, vh1, vh2, vh3);
                ldsm4t(stb + ST_VLO + voff, vl0, vl1, vl2, vl3);
                mma_bf(oacc[dt*2],   pah[s], vh0, vh1);
                mma_bf(oacc[dt*2+1], pah[s], vh2, vh3);
                mma_bf(oacc[dt*2],   pah[s], vl0, vl1);
                mma_bf(oacc[dt*2+1], pah[s], vl2, vl3);
                mma_bf(oacc[dt*2],   pal[s], vh0, vh1);
                mma_bf(oacc[dt*2+1], pal[s], vh2, vh3);
            }
        }

        cur_kb = n_kb; cur_half = n_half; buf ^= 1;
    }

    // ---- epilogue: quad-reduce l, write UNNORMALIZED partials ----
    lac0 += __shfl_xor_sync(0xffffffffu, lac0, 1);
    lac0 += __shfl_xor_sync(0xffffffffu, lac0, 2);
    lac1 += __shfl_xor_sync(0xffffffffu, lac1, 1);
    lac1 += __shfl_xor_sync(0xffffffffu, lac1, 2);

    const int q0 = qb * 64 + mbase + gid;
    float* o0 = OPART[sp] + ((size_t)bh * SQ + q0) * DH;
    float* o1 = o0 + 8 * DH;
    #pragma unroll
    for (int dt = 0; dt < 8; ++dt) {
        int col = dt * 8 + 2 * tig;
        *(float2*)(o0 + col) = make_float2(oacc[dt][0], oacc[dt][1]);
        *(float2*)(o1 + col) = make_float2(oacc[dt][2], oacc[dt][3]);
    }
    if (tig == 0) {
        LPART[sp][bh * SQ + q0]     = lac0;
        LPART[sp][bh * SQ + q0 + 8] = lac1;
    }
}

// ---- combine: Out = (O0+O1) / (l0+l1) ----
__global__ void __launch_bounds__(256)
combine(float* __restrict__ Out)
{
    int t = blockIdx.x * 256 + threadIdx.x;   // float4 index (16 per q-row)
    int qrow = t >> 4;
    float inv = 1.f / (LPART[0][qrow] + LPART[1][qrow]);
    float4 a = ((const float4*)OPART[0])[t];
    float4 b = ((const float4*)OPART[1])[t];
    float4 r = make_float4((a.x + b.x) * inv, (a.y + b.y) * inv,
                           (a.z + b.z) * inv, (a.w + b.w) * inv);
    ((float4*)Out)[t] = r;
}

extern "C" void kernel_launch(void* const* d_in, const int* in_sizes, int n_in,
                              void* d_out, int out_size)
{
    const float* q    = (const float*)d_in[0];
    const float* k    = (const float*)d_in[1];
    const float* v    = (const float*)d_in[2];
    const float* mask = (const float*)d_in[3];
    const int*   mat  = (const int*)  d_in[4];
    float* out = (float*)d_out;

    dim3 pgrid(NBLK, 16, 4);   // 2048 small CTAs: latency-hiding prepass
    prepass<<<pgrid, 128>>>(k, v);
    dim3 grid(NBLK, 16, 2);    // split-K parity: 1024 half-size CTAs
    bma_hmma<<<grid, 128>>>(q, mask, mat);
    combine<<<(16 * SQ * DH / 4) / 256, 256>>>(out);
}

// round 15
// speedup vs baseline: 1.2108x; 1.0172x over previous
#include <cuda_runtime.h>
#include <cuda_bf16.h>
#include <cstdint>

typedef unsigned int u32;

#define SQ   2048
#define DH   64
#define NBLK 32
#define L2E  1.4426950408889634f
#define BIG  (1e6f * L2E)

// static smem 48KB: Q hi/lo (16KB) + 2 K/V stage buffers (16KB each)
#define OFF_QHI 0
#define OFF_QLO 8192
#define OFF_ST  16384
#define ST_KHI  0
#define ST_KLO  4096
#define ST_VHI  8192
#define ST_VLO  12288

// pre-converted, pre-swizzled bf16 hi/lo tiles: [bh][kb] -> 8KB tile,
// 128B rows, keys [h*32,h*32+32) contiguous 4KB.
#define TILE_B 8192
__device__ __align__(16) char KHI_g[16 * 32 * TILE_B];
__device__ __align__(16) char KLO_g[16 * 32 * TILE_B];
__device__ __align__(16) char VHI_g[16 * 32 * TILE_B];
__device__ __align__(16) char VLO_g[16 * 32 * TILE_B];

// split-K partials: unnormalized O and l per (split, bh, q)
__device__ __align__(16) float OPART[2][16 * SQ * DH];
__device__ float LPART[2][16 * SQ];

__device__ __forceinline__ u32 swz(u32 x) { return x ^ ((x >> 3) & 0x70u); }
__device__ __forceinline__ u32 smem_u32(const void* p) {
    u32 a;
    asm("{ .reg .u64 t; cvta.to.shared.u64 t, %1; cvt.u32.u64 %0, t; }" : "=r"(a) : "l"(p));
    return a;
}
__device__ __forceinline__ float ex2(float x) {
    float r; asm("ex2.approx.f32 %0, %1;" : "=f"(r) : "f"(x)); return r;
}
__device__ __forceinline__ u32 bf2pack(float e0, float e1) {   // e0 -> low half
    u32 r; asm("cvt.rn.bf16x2.f32 %0, %1, %2;" : "=r"(r) : "f"(e1), "f"(e0)); return r;
}
__device__ __forceinline__ float bfrnd(float x) {
    return __bfloat162float(__float2bfloat16(x));
}
__device__ __forceinline__ void split4(float4 v, u32& h0, u32& h1, u32& l0, u32& l1) {
    h0 = bf2pack(v.x, v.y);
    h1 = bf2pack(v.z, v.w);
    l0 = bf2pack(v.x - bfrnd(v.x), v.y - bfrnd(v.y));
    l1 = bf2pack(v.z - bfrnd(v.z), v.w - bfrnd(v.w));
}
__device__ __forceinline__ void ldsm4(u32 a, u32& r0, u32& r1, u32& r2, u32& r3) {
    asm volatile("ldmatrix.sync.aligned.m8n8.x4.shared.b16 {%0,%1,%2,%3},[%4];"
                 : "=r"(r0), "=r"(r1), "=r"(r2), "=r"(r3) : "r"(a));
}
__device__ __forceinline__ void ldsm4t(u32 a, u32& r0, u32& r1, u32& r2, u32& r3) {
    asm volatile("ldmatrix.sync.aligned.m8n8.x4.trans.shared.b16 {%0,%1,%2,%3},[%4];"
                 : "=r"(r0), "=r"(r1), "=r"(r2), "=r"(r3) : "r"(a));
}
// not volatile — lets ptxas interleave independent-accumulator HMMAs
__device__ __forceinline__ void mma_bf(float* c, const u32* a, u32 b0, u32 b1) {
    asm("mma.sync.aligned.m16n8k16.row.col.f32.bf16.bf16.f32 "
        "{%0,%1,%2,%3},{%4,%5,%6,%7},{%8,%9},{%0,%1,%2,%3};"
        : "+f"(c[0]), "+f"(c[1]), "+f"(c[2]), "+f"(c[3])
        : "r"(a[0]), "r"(a[1]), "r"(a[2]), "r"(a[3]), "r"(b0), "r"(b1));
}
__device__ __forceinline__ void cpasync16(u32 dst, const void* src) {
    asm volatile("cp.async.cg.shared.global [%0], [%1], 16;" :: "r"(dst), "l"(src));
}

// ---- pre-pass v3: max-parallelism K/V fp32 -> bf16 hi/lo swizzled tiles.
// grid (NBLK, 16, 8): each CTA converts 8 rows; each thread 1 K + 1 V float4.
__global__ void __launch_bounds__(128)
prepass(const float* __restrict__ K, const float* __restrict__ V)
{
    const int kb = blockIdx.x, bh = blockIdx.y, zz = blockIdx.z;
    const int tid = threadIdx.x;
    const int row = zz * 8 + (tid >> 4);       // key row within 64
    const int c16 = tid & 15;                  // 16 threads per row
    const size_t src = ((size_t)bh * SQ + (size_t)kb * 64 + row) * DH + c16 * 4;
    const float4 kv4 = *(const float4*)(K + src);
    const float4 vv4 = *(const float4*)(V + src);
    const size_t tb = (size_t)(bh * NBLK + kb) * TILE_B;
    const u32 a = swz((u32)row * 128u + (u32)c16 * 8u);
    u32 h0, h1, l0, l1;
    split4(kv4, h0, h1, l0, l1);
    *(uint2*)(KHI_g + tb + a) = make_uint2(h0, h1);
    *(uint2*)(KLO_g + tb + a) = make_uint2(l0, l1);
    split4(vv4, h0, h1, l0, l1);
    *(uint2*)(VHI_g + tb + a) = make_uint2(h0, h1);
    *(uint2*)(VLO_g + tb + a) = make_uint2(l0, l1);
}

// Block-sparse flash attention (R9 structure), split-K by key-block parity.
// PV issues MMAs round-robin across all 8 O accumulators (reuse distance 8).
__global__ void __launch_bounds__(128, 4)
bma_hmma(const float* __restrict__ Q, const float* __restrict__ Mk,
         const int* __restrict__ Mat)
{
    __shared__ __align__(16) char smc[49152];
    const u32 smb = smem_u32(smc);

    const int tid  = threadIdx.x;
    const int lane = tid & 31;
    const int wid  = tid >> 5;
    const int gid  = lane >> 2;
    const int tig  = lane & 3;
    const int mbase = wid * 16;
    const int qb   = blockIdx.x;
    const int bh   = blockIdx.y;
    const int sp   = blockIdx.z;     // key-block parity split
    const int b    = bh >> 3;

    const float* Qp   = Q + ((size_t)bh * SQ + (size_t)qb * 64) * DH;
    const float* mrow = Mk + (size_t)b * SQ;
    const int* matrow = Mat + qb * NBLK;

    // ---- Q split -> Qhi/Qlo bf16, swizzled (once per CTA) ----
    {
        int row = tid >> 1, cb = (tid & 1) * 32;
        const float4* qs = (const float4*)(Qp + row * DH + cb);
        u32 rb = (u32)row * 128u + (u32)cb * 2u;
        #pragma unroll
        for (int i = 0; i < 8; ++i) {
            u32 h0, h1, l0, l1; split4(qs[i], h0, h1, l0, l1);
            u32 a = swz(rb + i * 8);
            *(uint2*)(smc + OFF_QHI + a) = make_uint2(h0, h1);
            *(uint2*)(smc + OFF_QLO + a) = make_uint2(l0, l1);
        }
    }

    float oacc[8][4];
    #pragma unroll
    for (int t = 0; t < 8; ++t)
        #pragma unroll
        for (int j = 0; j < 4; ++j) oacc[t][j] = 0.f;
    float lac0 = 0.f, lac1 = 0.f;

    const u32 aoffRow = (u32)(mbase + (lane & 15)) * 128u;
    const u32 aoffCol = (u32)((lane >> 4) * 8) * 2u;
    const u32 cpoff = (u32)tid * 32u;          // 4KB / 128 threads

    auto issue_stage = [&](int kb, int half, int sbuf) {
        const size_t g = (size_t)(bh * NBLK + kb) * TILE_B + (size_t)half * 4096 + cpoff;
        const u32 d = smb + OFF_ST + (u32)sbuf * 16384u + cpoff;
        cpasync16(d + ST_KHI,      KHI_g + g);
        cpasync16(d + ST_KHI + 16, KHI_g + g + 16);
        cpasync16(d + ST_KLO,      KLO_g + g);
        cpasync16(d + ST_KLO + 16, KLO_g + g + 16);
        cpasync16(d + ST_VHI,      VHI_g + g);
        cpasync16(d + ST_VHI + 16, VHI_g + g + 16);
        cpasync16(d + ST_VLO,      VLO_g + g);
        cpasync16(d + ST_VLO + 16, VLO_g + g + 16);
    };
    auto advance = [&](int& kb, int& hf) {
        hf ^= 1;
        if (hf == 0) { kb += 2; while (kb < NBLK && matrow[kb] == 0) kb += 2; }
    };

    // first active block of this parity (may not exist)
    int cur_kb = sp;
    while (cur_kb < NBLK && matrow[cur_kb] == 0) cur_kb += 2;
    int cur_half = 0;
    int buf = 0;

    if (cur_kb < NBLK) issue_stage(cur_kb, 0, 0);
    asm volatile("cp.async.commit_group;" ::: "memory");

    #pragma unroll 1
    while (cur_kb < NBLK) {
        int n_kb = cur_kb, n_half = cur_half;
        advance(n_kb, n_half);

        __syncthreads();                       // buf^1 free (prev stage consumed)
        if (n_kb < NBLK) issue_stage(n_kb, n_half, buf ^ 1);
        asm volatile("cp.async.commit_group;" ::: "memory");
        asm volatile("cp.async.wait_group 1;" ::: "memory");   // current arrived
        __syncthreads();

        const u32 stb = smb + OFF_ST + (u32)buf * 16384u;

        // ---- S = Q @ K^T (bf16, 3-term) ----
        float sacc[4][4];
        #pragma unroll
        for (int t = 0; t < 4; ++t)
            #pragma unroll
            for (int j = 0; j < 4; ++j) sacc[t][j] = 0.f;

        #pragma unroll
        for (int ks = 0; ks < 4; ++ks) {
            u32 ah[4], al[4];
            u32 aoff = swz(aoffRow + (u32)(ks * 16) * 2u + aoffCol);
            ldsm4(smb + OFF_QHI + aoff, ah[0], ah[1], ah[2], ah[3]);
            ldsm4(smb + OFF_QLO + aoff, al[0], al[1], al[2], al[3]);
            u32 kh[2][4], kl[2][4];
            #pragma unroll
            for (int g = 0; g < 2; ++g) {
                u32 boff = swz(
                    (u32)(g * 16 + ((lane >> 4) & 1) * 8 + (lane & 7)) * 128u +
                    (u32)(ks * 16 + ((lane >> 3) & 1) * 8) * 2u);
                ldsm4(stb + ST_KHI + boff, kh[g][0], kh[g][1], kh[g][2], kh[g][3]);
                ldsm4(stb + ST_KLO + boff, kl[g][0], kl[g][1], kl[g][2], kl[g][3]);
            }
            mma_bf(sacc[0], ah, kh[0][0], kh[0][1]);
            mma_bf(sacc[1], ah, kh[0][2], kh[0][3]);
            mma_bf(sacc[2], ah, kh[1][0], kh[1][1]);
            mma_bf(sacc[3], ah, kh[1][2], kh[1][3]);
            mma_bf(sacc[0], ah, kl[0][0], kl[0][1]);
            mma_bf(sacc[1], ah, kl[0][2], kl[0][3]);
            mma_bf(sacc[2], ah, kl[1][0], kl[1][1]);
            mma_bf(sacc[3], ah, kl[1][2], kl[1][3]);
            mma_bf(sacc[0], al, kh[0][0], kh[0][1]);
            mma_bf(sacc[1], al, kh[0][2], kh[0][3]);
            mma_bf(sacc[2], al, kh[1][0], kh[1][1]);
            mma_bf(sacc[3], al, kh[1][2], kh[1][3]);
        }

        // ---- softmax; P packed to bf16 hi/lo A-fragments in-register ----
        u32 pah[2][4], pal[2][4];
        #pragma unroll
        for (int nt = 0; nt < 4; ++nt) {
            const float2 mb =
                *(const float2*)(mrow + cur_kb * 64 + cur_half * 32 + nt * 8 + 2 * tig);
            float b0 = (mb.x - 1.f) * BIG;
            float b1 = (mb.y - 1.f) * BIG;
            float p0 = ex2(fmaf(sacc[nt][0], L2E, b0));
            float p1 = ex2(fmaf(sacc[nt][1], L2E, b1));
            float p2 = ex2(fmaf(sacc[nt][2], L2E, b0));
            float p3 = ex2(fmaf(sacc[nt][3], L2E, b1));
            lac0 += p0 + p1;
            lac1 += p2 + p3;
            int s = nt >> 1, hb = (nt & 1) * 2;
            pah[s][hb+0] = bf2pack(p0, p1);
            pah[s][hb+1] = bf2pack(p2, p3);
            pal[s][hb+0] = bf2pack(p0 - bfrnd(p0), p1 - bfrnd(p1));
            pal[s][hb+1] = bf2pack(p2 - bfrnd(p2), p3 - bfrnd(p3));
        }

        // ---- O += P @ V (bf16, 3-term), 8-accumulator round-robin ----
        // Load ALL V fragments for a 16-key slab first (sacc is dead: regs free),
        // then issue 24 MMAs at reuse distance 8 per accumulator.
        #pragma unroll
        for (int s = 0; s < 2; ++s) {
            u32 vh[4][4], vl[4][4];
            #pragma unroll
            for (int dt = 0; dt < 4; ++dt) {
                u32 voff = swz(
                    (u32)(s * 16 + ((lane >> 3) & 1) * 8 + (lane & 7)) * 128u +
                    (u32)(dt * 16 + ((lane >> 4) & 1) * 8) * 2u);
                ldsm4t(stb + ST_VHI + voff, vh[dt][0], vh[dt][1], vh[dt][2], vh[dt][3]);
                ldsm4t(stb + ST_VLO + voff, vl[dt][0], vl[dt][1], vl[dt][2], vl[dt][3]);
            }
            #pragma unroll
            for (int dt = 0; dt < 4; ++dt) {
                mma_bf(oacc[dt*2],   pah[s], vh[dt][0], vh[dt][1]);
                mma_bf(oacc[dt*2+1], pah[s], vh[dt][2], vh[dt][3]);
            }
            #pragma unroll
            for (int dt = 0; dt < 4; ++dt) {
                mma_bf(oacc[dt*2],   pah[s], vl[dt][0], vl[dt][1]);
                mma_bf(oacc[dt*2+1], pah[s], vl[dt][2], vl[dt][3]);
            }
            #pragma unroll
            for (int dt = 0; dt < 4; ++dt) {
                mma_bf(oacc[dt*2],   pal[s], vh[dt][0], vh[dt][1]);
                mma_bf(oacc[dt*2+1], pal[s], vh[dt][2], vh[dt][3]);
            }
        }

        cur_kb = n_kb; cur_half = n_half; buf ^= 1;
    }

    // ---- epilogue: quad-reduce l, write UNNORMALIZED partials ----
    lac0 += __shfl_xor_sync(0xffffffffu, lac0, 1);
    lac0 += __shfl_xor_sync(0xffffffffu, lac0, 2);
    lac1 += __shfl_xor_sync(0xffffffffu, lac1, 1);
    lac1 += __shfl_xor_sync(0xffffffffu, lac1, 2);

    const int q0 = qb * 64 + mbase + gid;
    float* o0 = OPART[sp] + ((size_t)bh * SQ + q0) * DH;
    float* o1 = o0 + 8 * DH;
    #pragma unroll
    for (int dt = 0; dt < 8; ++dt) {
        int col = dt * 8 + 2 * tig;
        *(float2*)(o0 + col) = make_float2(oacc[dt][0], oacc[dt][1]);
        *(float2*)(o1 + col) = make_float2(oacc[dt][2], oacc[dt][3]);
    }
    if (tig == 0) {
        LPART[sp][bh * SQ + q0]     = lac0;
        LPART[sp][bh * SQ + q0 + 8] = lac1;
    }
}

// ---- combine: Out = (O0+O1) / (l0+l1) ----
__global__ void __launch_bounds__(256)
combine(float* __restrict__ Out)
{
    int t = blockIdx.x * 256 + threadIdx.x;   // float4 index (16 per q-row)
    int qrow = t >> 4;
    float inv = 1.f / (LPART[0][qrow] + LPART[1][qrow]);
    float4 a = ((const float4*)OPART[0])[t];
    float4 b = ((const float4*)OPART[1])[t];
    float4 r = make_float4((a.x + b.x) * inv, (a.y + b.y) * inv,
                           (a.z + b.z) * inv, (a.w + b.w) * inv);
    ((float4*)Out)[t] = r;
}

extern "C" void kernel_launch(void* const* d_in, const int* in_sizes, int n_in,
                              void* d_out, int out_size)
{
    const float* q    = (const float*)d_in[0];
    const float* k    = (const float*)d_in[1];
    const float* v    = (const float*)d_in[2];
    const float* mask = (const float*)d_in[3];
    const int*   mat  = (const int*)  d_in[4];
    float* out = (float*)d_out;

    dim3 pgrid(NBLK, 16, 8);   // 4096 tiny CTAs: latency-hiding prepass
    prepass<<<pgrid, 128>>>(k, v);
    dim3 grid(NBLK, 16, 2);    // split-K parity: 1024 half-size CTAs
    bma_hmma<<<grid, 128>>>(q, mask, mat);
    combine<<<(16 * SQ * DH / 4) / 256, 256>>>(out);
}

// round 16
// speedup vs baseline: 1.2195x; 1.0072x over previous
#include <cuda_runtime.h>
#include <cuda_bf16.h>
#include <cstdint>

typedef unsigned int u32;

#define SQ   2048
#define DH   64
#define NBLK 32
#define NSP  4
#define L2E  1.4426950408889634f
#define BIG  (1e6f * L2E)

// static smem 48KB: Q hi/lo (16KB) + 2 K/V stage buffers (16KB each)
#define OFF_QHI 0
#define OFF_QLO 8192
#define OFF_ST  16384
#define ST_KHI  0
#define ST_KLO  4096
#define ST_VHI  8192
#define ST_VLO  12288

// pre-converted, pre-swizzled bf16 hi/lo tiles: [bh][kb] -> 8KB tile,
// 128B rows, keys [h*32,h*32+32) contiguous 4KB.
#define TILE_B 8192
__device__ __align__(16) char KHI_g[16 * 32 * TILE_B];
__device__ __align__(16) char KLO_g[16 * 32 * TILE_B];
__device__ __align__(16) char VHI_g[16 * 32 * TILE_B];
__device__ __align__(16) char VLO_g[16 * 32 * TILE_B];

// split-K partials: unnormalized O and l per (split, bh, q)
__device__ __align__(16) float OPART[NSP][16 * SQ * DH];
__device__ float LPART[NSP][16 * SQ];

__device__ __forceinline__ u32 swz(u32 x) { return x ^ ((x >> 3) & 0x70u); }
__device__ __forceinline__ u32 smem_u32(const void* p) {
    u32 a;
    asm("{ .reg .u64 t; cvta.to.shared.u64 t, %1; cvt.u32.u64 %0, t; }" : "=r"(a) : "l"(p));
    return a;
}
__device__ __forceinline__ float ex2(float x) {
    float r; asm("ex2.approx.f32 %0, %1;" : "=f"(r) : "f"(x)); return r;
}
__device__ __forceinline__ u32 bf2pack(float e0, float e1) {   // e0 -> low half
    u32 r; asm("cvt.rn.bf16x2.f32 %0, %1, %2;" : "=r"(r) : "f"(e1), "f"(e0)); return r;
}
__device__ __forceinline__ float bfrnd(float x) {
    return __bfloat162float(__float2bfloat16(x));
}
__device__ __forceinline__ void split4(float4 v, u32& h0, u32& h1, u32& l0, u32& l1) {
    h0 = bf2pack(v.x, v.y);
    h1 = bf2pack(v.z, v.w);
    l0 = bf2pack(v.x - bfrnd(v.x), v.y - bfrnd(v.y));
    l1 = bf2pack(v.z - bfrnd(v.z), v.w - bfrnd(v.w));
}
__device__ __forceinline__ void ldsm4(u32 a, u32& r0, u32& r1, u32& r2, u32& r3) {
    asm volatile("ldmatrix.sync.aligned.m8n8.x4.shared.b16 {%0,%1,%2,%3},[%4];"
                 : "=r"(r0), "=r"(r1), "=r"(r2), "=r"(r3) : "r"(a));
}
__device__ __forceinline__ void ldsm4t(u32 a, u32& r0, u32& r1, u32& r2, u32& r3) {
    asm volatile("ldmatrix.sync.aligned.m8n8.x4.trans.shared.b16 {%0,%1,%2,%3},[%4];"
                 : "=r"(r0), "=r"(r1), "=r"(r2), "=r"(r3) : "r"(a));
}
// not volatile — lets ptxas interleave independent-accumulator HMMAs
__device__ __forceinline__ void mma_bf(float* c, const u32* a, u32 b0, u32 b1) {
    asm("mma.sync.aligned.m16n8k16.row.col.f32.bf16.bf16.f32 "
        "{%0,%1,%2,%3},{%4,%5,%6,%7},{%8,%9},{%0,%1,%2,%3};"
        : "+f"(c[0]), "+f"(c[1]), "+f"(c[2]), "+f"(c[3])
        : "r"(a[0]), "r"(a[1]), "r"(a[2]), "r"(a[3]), "r"(b0), "r"(b1));
}
__device__ __forceinline__ void cpasync16(u32 dst, const void* src) {
    asm volatile("cp.async.cg.shared.global [%0], [%1], 16;" :: "r"(dst), "l"(src));
}

// ---- pre-pass: max-parallelism K/V fp32 -> bf16 hi/lo swizzled tiles.
// grid (NBLK, 16, 8): each CTA converts 8 rows; each thread 1 K + 1 V float4.
__global__ void __launch_bounds__(128)
prepass(const float* __restrict__ K, const float* __restrict__ V)
{
    const int kb = blockIdx.x, bh = blockIdx.y, zz = blockIdx.z;
    const int tid = threadIdx.x;
    const int row = zz * 8 + (tid >> 4);       // key row within 64
    const int c16 = tid & 15;                  // 16 threads per row
    const size_t src = ((size_t)bh * SQ + (size_t)kb * 64 + row) * DH + c16 * 4;
    const float4 kv4 = *(const float4*)(K + src);
    const float4 vv4 = *(const float4*)(V + src);
    const size_t tb = (size_t)(bh * NBLK + kb) * TILE_B;
    const u32 a = swz((u32)row * 128u + (u32)c16 * 8u);
    u32 h0, h1, l0, l1;
    split4(kv4, h0, h1, l0, l1);
    *(uint2*)(KHI_g + tb + a) = make_uint2(h0, h1);
    *(uint2*)(KLO_g + tb + a) = make_uint2(l0, l1);
    split4(vv4, h0, h1, l0, l1);
    *(uint2*)(VHI_g + tb + a) = make_uint2(h0, h1);
    *(uint2*)(VLO_g + tb + a) = make_uint2(l0, l1);
}

// Block-sparse flash attention, split-K 4 ways by key-block residue (kb%4==sp).
// Writes unnormalized partials. 2-buffer cp.async pipeline, bf16 3-term HMMA,
// PV round-robin across all 8 O accumulators.
__global__ void __launch_bounds__(128, 4)
bma_hmma(const float* __restrict__ Q, const float* __restrict__ Mk,
         const int* __restrict__ Mat)
{
    __shared__ __align__(16) char smc[49152];
    const u32 smb = smem_u32(smc);

    const int tid  = threadIdx.x;
    const int lane = tid & 31;
    const int wid  = tid >> 5;
    const int gid  = lane >> 2;
    const int tig  = lane & 3;
    const int mbase = wid * 16;
    const int qb   = blockIdx.x;
    const int bh   = blockIdx.y;
    const int sp   = blockIdx.z;     // key-block residue split (0..3)
    const int b    = bh >> 3;

    const float* Qp   = Q + ((size_t)bh * SQ + (size_t)qb * 64) * DH;
    const float* mrow = Mk + (size_t)b * SQ;
    const int* matrow = Mat + qb * NBLK;

    // ---- Q split -> Qhi/Qlo bf16, swizzled (once per CTA) ----
    {
        int row = tid >> 1, cb = (tid & 1) * 32;
        const float4* qs = (const float4*)(Qp + row * DH + cb);
        u32 rb = (u32)row * 128u + (u32)cb * 2u;
        #pragma unroll
        for (int i = 0; i < 8; ++i) {
            u32 h0, h1, l0, l1; split4(qs[i], h0, h1, l0, l1);
            u32 a = swz(rb + i * 8);
            *(uint2*)(smc + OFF_QHI + a) = make_uint2(h0, h1);
            *(uint2*)(smc + OFF_QLO + a) = make_uint2(l0, l1);
        }
    }

    float oacc[8][4];
    #pragma unroll
    for (int t = 0; t < 8; ++t)
        #pragma unroll
        for (int j = 0; j < 4; ++j) oacc[t][j] = 0.f;
    float lac0 = 0.f, lac1 = 0.f;

    const u32 aoffRow = (u32)(mbase + (lane & 15)) * 128u;
    const u32 aoffCol = (u32)((lane >> 4) * 8) * 2u;
    const u32 cpoff = (u32)tid * 32u;          // 4KB / 128 threads

    auto issue_stage = [&](int kb, int half, int sbuf) {
        const size_t g = (size_t)(bh * NBLK + kb) * TILE_B + (size_t)half * 4096 + cpoff;
        const u32 d = smb + OFF_ST + (u32)sbuf * 16384u + cpoff;
        cpasync16(d + ST_KHI,      KHI_g + g);
        cpasync16(d + ST_KHI + 16, KHI_g + g + 16);
        cpasync16(d + ST_KLO,      KLO_g + g);
        cpasync16(d + ST_KLO + 16, KLO_g + g + 16);
        cpasync16(d + ST_VHI,      VHI_g + g);
        cpasync16(d + ST_VHI + 16, VHI_g + g + 16);
        cpasync16(d + ST_VLO,      VLO_g + g);
        cpasync16(d + ST_VLO + 16, VLO_g + g + 16);
    };
    auto advance = [&](int& kb, int& hf) {
        hf ^= 1;
        if (hf == 0) { kb += NSP; while (kb < NBLK && matrow[kb] == 0) kb += NSP; }
    };

    // first active block of this residue class (may not exist)
    int cur_kb = sp;
    while (cur_kb < NBLK && matrow[cur_kb] == 0) cur_kb += NSP;
    int cur_half = 0;
    int buf = 0;

    if (cur_kb < NBLK) issue_stage(cur_kb, 0, 0);
    asm volatile("cp.async.commit_group;" ::: "memory");

    #pragma unroll 1
    while (cur_kb < NBLK) {
        int n_kb = cur_kb, n_half = cur_half;
        advance(n_kb, n_half);

        __syncthreads();                       // buf^1 free (prev stage consumed)
        if (n_kb < NBLK) issue_stage(n_kb, n_half, buf ^ 1);
        asm volatile("cp.async.commit_group;" ::: "memory");
        asm volatile("cp.async.wait_group 1;" ::: "memory");   // current arrived
        __syncthreads();

        const u32 stb = smb + OFF_ST + (u32)buf * 16384u;

        // ---- S = Q @ K^T (bf16, 3-term) ----
        float sacc[4][4];
        #pragma unroll
        for (int t = 0; t < 4; ++t)
            #pragma unroll
            for (int j = 0; j < 4; ++j) sacc[t][j] = 0.f;

        #pragma unroll
        for (int ks = 0; ks < 4; ++ks) {
            u32 ah[4], al[4];
            u32 aoff = swz(aoffRow + (u32)(ks * 16) * 2u + aoffCol);
            ldsm4(smb + OFF_QHI + aoff, ah[0], ah[1], ah[2], ah[3]);
            ldsm4(smb + OFF_QLO + aoff, al[0], al[1], al[2], al[3]);
            u32 kh[2][4], kl[2][4];
            #pragma unroll
            for (int g = 0; g < 2; ++g) {
                u32 boff = swz(
                    (u32)(g * 16 + ((lane >> 4) & 1) * 8 + (lane & 7)) * 128u +
                    (u32)(ks * 16 + ((lane >> 3) & 1) * 8) * 2u);
                ldsm4(stb + ST_KHI + boff, kh[g][0], kh[g][1], kh[g][2], kh[g][3]);
                ldsm4(stb + ST_KLO + boff, kl[g][0], kl[g][1], kl[g][2], kl[g][3]);
            }
            mma_bf(sacc[0], ah, kh[0][0], kh[0][1]);
            mma_bf(sacc[1], ah, kh[0][2], kh[0][3]);
            mma_bf(sacc[2], ah, kh[1][0], kh[1][1]);
            mma_bf(sacc[3], ah, kh[1][2], kh[1][3]);
            mma_bf(sacc[0], ah, kl[0][0], kl[0][1]);
            mma_bf(sacc[1], ah, kl[0][2], kl[0][3]);
            mma_bf(sacc[2], ah, kl[1][0], kl[1][1]);
            mma_bf(sacc[3], ah, kl[1][2], kl[1][3]);
            mma_bf(sacc[0], al, kh[0][0], kh[0][1]);
            mma_bf(sacc[1], al, kh[0][2], kh[0][3]);
            mma_bf(sacc[2], al, kh[1][0], kh[1][1]);
            mma_bf(sacc[3], al, kh[1][2], kh[1][3]);
        }

        // ---- softmax; P packed to bf16 hi/lo A-fragments in-register ----
        u32 pah[2][4], pal[2][4];
        #pragma unroll
        for (int nt = 0; nt < 4; ++nt) {
            const float2 mb =
                *(const float2*)(mrow + cur_kb * 64 + cur_half * 32 + nt * 8 + 2 * tig);
            float b0 = (mb.x - 1.f) * BIG;
            float b1 = (mb.y - 1.f) * BIG;
            float p0 = ex2(fmaf(sacc[nt][0], L2E, b0));
            float p1 = ex2(fmaf(sacc[nt][1], L2E, b1));
            float p2 = ex2(fmaf(sacc[nt][2], L2E, b0));
            float p3 = ex2(fmaf(sacc[nt][3], L2E, b1));
            lac0 += p0 + p1;
            lac1 += p2 + p3;
            int s = nt >> 1, hb = (nt & 1) * 2;
            pah[s][hb+0] = bf2pack(p0, p1);
            pah[s][hb+1] = bf2pack(p2, p3);
            pal[s][hb+0] = bf2pack(p0 - bfrnd(p0), p1 - bfrnd(p1));
            pal[s][hb+1] = bf2pack(p2 - bfrnd(p2), p3 - bfrnd(p3));
        }

        // ---- O += P @ V (bf16, 3-term), 8-accumulator round-robin ----
        #pragma unroll
        for (int s = 0; s < 2; ++s) {
            u32 vh[4][4], vl[4][4];
            #pragma unroll
            for (int dt = 0; dt < 4; ++dt) {
                u32 voff = swz(
                    (u32)(s * 16 + ((lane >> 3) & 1) * 8 + (lane & 7)) * 128u +
                    (u32)(dt * 16 + ((lane >> 4) & 1) * 8) * 2u);
                ldsm4t(stb + ST_VHI + voff, vh[dt][0], vh[dt][1], vh[dt][2], vh[dt][3]);
                ldsm4t(stb + ST_VLO + voff, vl[dt][0], vl[dt][1], vl[dt][2], vl[dt][3]);
            }
            #pragma unroll
            for (int dt = 0; dt < 4; ++dt) {
                mma_bf(oacc[dt*2],   pah[s], vh[dt][0], vh[dt][1]);
                mma_bf(oacc[dt*2+1], pah[s], vh[dt][2], vh[dt][3]);
            }
            #pragma unroll
            for (int dt = 0; dt < 4; ++dt) {
                mma_bf(oacc[dt*2],   pah[s], vl[dt][0], vl[dt][1]);
                mma_bf(oacc[dt*2+1], pah[s], vl[dt][2], vl[dt][3]);
            }
            #pragma unroll
            for (int dt = 0; dt < 4; ++dt) {
                mma_bf(oacc[dt*2],   pal[s], vh[dt][0], vh[dt][1]);
                mma_bf(oacc[dt*2+1], pal[s], vh[dt][2], vh[dt][3]);
            }
        }

        cur_kb = n_kb; cur_half = n_half; buf ^= 1;
    }

    // ---- epilogue: quad-reduce l, write UNNORMALIZED partials ----
    lac0 += __shfl_xor_sync(0xffffffffu, lac0, 1);
    lac0 += __shfl_xor_sync(0xffffffffu, lac0, 2);
    lac1 += __shfl_xor_sync(0xffffffffu, lac1, 1);
    lac1 += __shfl_xor_sync(0xffffffffu, lac1, 2);

    const int q0 = qb * 64 + mbase + gid;
    float* o0 = OPART[sp] + ((size_t)bh * SQ + q0) * DH;
    float* o1 = o0 + 8 * DH;
    #pragma unroll
    for (int dt = 0; dt < 8; ++dt) {
        int col = dt * 8 + 2 * tig;
        *(float2*)(o0 + col) = make_float2(oacc[dt][0], oacc[dt][1]);
        *(float2*)(o1 + col) = make_float2(oacc[dt][2], oacc[dt][3]);
    }
    if (tig == 0) {
        LPART[sp][bh * SQ + q0]     = lac0;
        LPART[sp][bh * SQ + q0 + 8] = lac1;
    }
}

// ---- combine: Out = (O0+O1+O2+O3) / (l0+l1+l2+l3) ----
__global__ void __launch_bounds__(256)
combine(float* __restrict__ Out)
{
    int t = blockIdx.x * 256 + threadIdx.x;   // float4 index (16 per q-row)
    int qrow = t >> 4;
    float inv = 1.f / (LPART[0][qrow] + LPART[1][qrow] +
                       LPART[2][qrow] + LPART[3][qrow]);
    float4 a = ((const float4*)OPART[0])[t];
    float4 b = ((const float4*)OPART[1])[t];
    float4 c = ((const float4*)OPART[2])[t];
    float4 d = ((const float4*)OPART[3])[t];
    float4 r = make_float4((a.x + b.x + c.x + d.x) * inv,
                           (a.y + b.y + c.y + d.y) * inv,
                           (a.z + b.z + c.z + d.z) * inv,
                           (a.w + b.w + c.w + d.w) * inv);
    ((float4*)Out)[t] = r;
}

extern "C" void kernel_launch(void* const* d_in, const int* in_sizes, int n_in,
                              void* d_out, int out_size)
{
    const float* q    = (const float*)d_in[0];
    const float* k    = (const float*)d_in[1];
    const float* v    = (const float*)d_in[2];
    const float* mask = (const float*)d_in[3];
    const int*   mat  = (const int*)  d_in[4];
    float* out = (float*)d_out;

    dim3 pgrid(NBLK, 16, 8);    // 4096 tiny CTAs: latency-hiding prepass
    prepass<<<pgrid, 128>>>(k, v);
    dim3 grid(NBLK, 16, NSP);   // 4-way split-K: 2048 fine-grained CTAs
    bma_hmma<<<grid, 128>>>(q, mask, mat);
    combine<<<(16 * SQ * DH / 4) / 256, 256>>>(out);
}